// round 8
// baseline (speedup 1.0000x reference)
#include <cuda_runtime.h>

#define HID 64
#define NMAX 100000
#define EMAX 3200000

// ---- scratch (device globals: no allocation allowed; 16B-aligned for v4 ops) ----
__device__ __align__(16) float g_dis[NMAX];       // degree accumulator, then rsqrt(deg)
__device__ __align__(16) float g_f[NMAX * HID];   // pre-aggregation features
__device__ __align__(16) float g_g[NMAX * HID];   // aggregation accumulator
__device__ __align__(16) float g_A[NMAX * HID];   // h2 @ Wm1[0:64]
__device__ __align__(16) float g_B[NMAX * HID];   // h2 @ Wm1[64:128]
__device__ int   g_src[EMAX];          // int32 src indices
__device__ int   g_dst[EMAX];          // int32 dst indices
__device__ float g_nrm[EMAX];          // per-edge norm = dis[s]*dis[d]

// ---------------------------------------------------------------------------
__global__ void k_deg_init(int n) {
    int i = blockIdx.x * blockDim.x + threadIdx.x;
    if (i < n) g_dis[i] = 1.0f;  // self-loop contributes 1 to in-degree
}

// copy int32 indices into scratch AND accumulate in-degree
__global__ void k_prep(const int* __restrict__ ei, int E) {
    int i = blockIdx.x * blockDim.x + threadIdx.x;
    if (i < E) {
        int s = ei[i];
        int d = ei[E + i];
        g_src[i] = s;
        g_dst[i] = d;
        atomicAdd(&g_dis[d], 1.0f);
    }
}

__global__ void k_rsqrt(int n) {
    int i = blockIdx.x * blockDim.x + threadIdx.x;
    if (i < n) g_dis[i] = rsqrtf(g_dis[i]);
}

__global__ void k_norm(int E) {
    int i = blockIdx.x * blockDim.x + threadIdx.x;
    if (i < E) g_nrm[i] = g_dis[g_src[i]] * g_dis[g_dst[i]];
}

// ---------------------------------------------------------------------------
// layer-1 input GEMM fused with self-loop init:
//   f = x @ W1 ;  g_f = f ;  g_g = f * dis[v]^2
__global__ void k_gemm4_agg(const float* __restrict__ x, const float* __restrict__ W, int n) {
    __shared__ float sW[4 * HID];
    int t = threadIdx.x;
    if (t < 4 * HID) sW[t] = W[t];
    __syncthreads();
    int idx = blockIdx.x * blockDim.x + t;
    if (idx < n * HID) {
        int v = idx >> 6, c = idx & 63;
        float4 xv = ((const float4*)x)[v];
        float f = xv.x * sW[c] + xv.y * sW[64 + c] + xv.z * sW[128 + c] + xv.w * sW[192 + c];
        float d = g_dis[v];
        g_f[idx] = f;
        g_g[idx] = f * d * d;
    }
}

// ---------------------------------------------------------------------------
// 2 edges per warp, 16 lanes per edge, float4 gather + red.v4 scatter:
// g_g[dst] += g_f[src] * nrm
__global__ void k_agg_edges(int E) {
    int gt = blockIdx.x * blockDim.x + threadIdx.x;
    int w = gt >> 5;
    int lane = gt & 31;
    int half = lane >> 4;          // which edge within the warp
    int l = lane & 15;             // lane within edge (16 x float4 = 64 floats)
    int e = w * 2 + half;
    if (e < E) {
        int s = g_src[e];
        int d = g_dst[e];
        float nrm = g_nrm[e];
        float4 v = ((const float4*)(g_f + s * HID))[l];
        float* gp = g_g + d * HID + l * 4;
        asm volatile("red.global.add.v4.f32 [%0], {%1, %2, %3, %4};"
                     :: "l"(gp), "f"(v.x * nrm), "f"(v.y * nrm),
                        "f"(v.z * nrm), "f"(v.w * nrm)
                     : "memory");
    }
}

// ---------------------------------------------------------------------------
// layer-2 GEMM fused on both sides:
//   h1 = relu(g_g + b1)          (applied while staging the input tile)
//   f2 = h1 @ W2
//   g_f = f2 ; g_g = f2 * dis^2  (self-loop init for layer-2 aggregation)
// Safe in-place: each block writes only the rows it staged.
__global__ void k_gemm64_relu_agg(const float* __restrict__ W,
                                  const float* __restrict__ bias, int n) {
    __shared__ float sW[HID * HID];
    __shared__ float sx[8][HID];
    __shared__ float sb[HID];
    int t = threadIdx.x;
    for (int i = t; i < HID * HID; i += 256) sW[i] = W[i];
    if (t < HID) sb[t] = bias[t];
    int ty = t >> 5, tx = t & 31;
    for (int base = blockIdx.x * 8; base < n; base += gridDim.x * 8) {
        __syncthreads();
        for (int i = t; i < 8 * HID; i += 256) {
            int r = i >> 6, c = i & 63;
            int v = base + r;
            sx[r][c] = (v < n) ? fmaxf(g_g[v * HID + c] + sb[c], 0.f) : 0.f;
        }
        __syncthreads();
        int v = base + ty;
        if (v < n) {
            float a0 = 0.f, a1 = 0.f;
#pragma unroll
            for (int k = 0; k < HID; k++) {
                float xv = sx[ty][k];
                a0 += xv * sW[k * HID + tx];
                a1 += xv * sW[k * HID + tx + 32];
            }
            float d = g_dis[v];
            float dd = d * d;
            g_f[v * HID + tx]      = a0;
            g_f[v * HID + tx + 32] = a1;
            g_g[v * HID + tx]      = a0 * dd;
            g_g[v * HID + tx + 32] = a1 * dd;
        }
    }
}

// ---------------------------------------------------------------------------
// final projections fused with bias+relu on load:
//   h2 = relu(g_g + b2) ; g_A = h2 @ WA ; g_B = h2 @ WB
__global__ void k_gemm64x2_relu(const float* __restrict__ WA, const float* __restrict__ WB,
                                const float* __restrict__ bias, int n) {
    __shared__ float sWA[HID * HID];
    __shared__ float sWB[HID * HID];
    __shared__ float sx[8][HID];
    __shared__ float sb[HID];
    int t = threadIdx.x;
    for (int i = t; i < HID * HID; i += 256) { sWA[i] = WA[i]; sWB[i] = WB[i]; }
    if (t < HID) sb[t] = bias[t];
    int ty = t >> 5, tx = t & 31;
    for (int base = blockIdx.x * 8; base < n; base += gridDim.x * 8) {
        __syncthreads();
        for (int i = t; i < 8 * HID; i += 256) {
            int r = i >> 6, c = i & 63;
            int v = base + r;
            sx[r][c] = (v < n) ? fmaxf(g_g[v * HID + c] + sb[c], 0.f) : 0.f;
        }
        __syncthreads();
        int v = base + ty;
        if (v < n) {
            float a0 = 0.f, a1 = 0.f, b0 = 0.f, b1 = 0.f;
#pragma unroll
            for (int k = 0; k < HID; k++) {
                float xv = sx[ty][k];
                a0 += xv * sWA[k * HID + tx];
                a1 += xv * sWA[k * HID + tx + 32];
                b0 += xv * sWB[k * HID + tx];
                b1 += xv * sWB[k * HID + tx + 32];
            }
            g_A[v * HID + tx]      = a0;
            g_A[v * HID + tx + 32] = a1;
            g_B[v * HID + tx]      = b0;
            g_B[v * HID + tx + 32] = b1;
        }
    }
}

// ---------------------------------------------------------------------------
// per-edge MLP, 2 edges/warp, float4 gathers, single float2 store per warp:
// out[e] = relu(A[src] + B[dst] + edge_attr@Wm1c + bm1) @ Wm2 + bm2
__global__ void k_edge_mlp(const float* __restrict__ eattr,
                           const float* __restrict__ Wm1, const float* __restrict__ bm1,
                           const float* __restrict__ Wm2, const float* __restrict__ bm2,
                           float* __restrict__ out, int E) {
    __shared__ float sWc[4 * HID];
    __shared__ float sb[HID];
    __shared__ float sW2[HID];
    __shared__ float sb2;
    int t = threadIdx.x;
    if (t < 4 * HID) sWc[t] = Wm1[128 * HID + t];
    if (t < HID) { sb[t] = bm1[t]; sW2[t] = Wm2[t]; }
    if (t == 0) sb2 = bm2[0];
    __syncthreads();

    int lane = t & 31;
    int half = lane >> 4;
    int l = lane & 15;
    int c0 = l * 4;
    int w = (blockIdx.x * blockDim.x + t) >> 5;
    int nw = (gridDim.x * blockDim.x) >> 5;
    for (int ew = w; ew * 2 < E; ew += nw) {
        int e = ew * 2 + half;
        float p = 0.f;
        if (e < E) {
            int s = g_src[e];
            int d = g_dst[e];
            float4 ea = ((const float4*)eattr)[e];
            float4 a = ((const float4*)(g_A + s * HID))[l];
            float4 b = ((const float4*)(g_B + d * HID))[l];
            float za[4] = {a.x + b.x, a.y + b.y, a.z + b.z, a.w + b.w};
#pragma unroll
            for (int j = 0; j < 4; j++) {
                int c = c0 + j;
                float z = za[j] + sb[c]
                        + ea.x * sWc[c] + ea.y * sWc[64 + c]
                        + ea.z * sWc[128 + c] + ea.w * sWc[192 + c];
                p += fmaxf(z, 0.f) * sW2[c];
            }
        }
        // reduce over 16 lanes within each half-warp
#pragma unroll
        for (int o = 8; o; o >>= 1) p += __shfl_xor_sync(0xffffffffu, p, o);
        // lane 16 holds edge e1's result; bring it to lane 0 and emit one 8B store
        float p1 = __shfl_sync(0xffffffffu, p, 16);
        if (lane == 0) {
            int e0 = ew * 2;
            if (e0 + 1 < E) {
                ((float2*)(out + e0))[0] = make_float2(p + sb2, p1 + sb2);
            } else if (e0 < E) {
                out[e0] = p + sb2;
            }
        }
    }
}

// ---------------------------------------------------------------------------
extern "C" void kernel_launch(void* const* d_in, const int* in_sizes, int n_in,
                              void* d_out, int out_size) {
    const float* x    = (const float*)d_in[0];
    const int*   ei   = (const int*)d_in[1];      // int32 (jax x64 disabled)
    const float* ea   = (const float*)d_in[2];
    const float* W1   = (const float*)d_in[3];
    const float* b1   = (const float*)d_in[4];
    const float* W2   = (const float*)d_in[5];
    const float* b2   = (const float*)d_in[6];
    const float* Wm1  = (const float*)d_in[7];
    const float* bm1  = (const float*)d_in[8];
    const float* Wm2  = (const float*)d_in[9];
    const float* bm2  = (const float*)d_in[10];
    float* out = (float*)d_out;

    int n = in_sizes[0] / 4;     // x is [n,4]
    int E = in_sizes[1] / 2;     // edge_index is [2,E]

    const int T = 256;
    int gb_n   = (n + T - 1) / T;
    int gb_nh  = (n * HID + T - 1) / T;
    int gb_e   = (E + T - 1) / T;
    int nwarp  = (E + 1) / 2;                    // 2 edges per warp
    int gb_ew  = (nwarp * 32 + T - 1) / T;

    // degrees / norm (+ index copy)
    k_deg_init<<<gb_n, T>>>(n);
    k_prep<<<gb_e, T>>>(ei, E);
    k_rsqrt<<<gb_n, T>>>(n);
    k_norm<<<gb_e, T>>>(E);

    // layer 1: input GEMM (+ self-loop init), then edge scatter
    k_gemm4_agg<<<gb_nh, T>>>(x, W1, n);
    k_agg_edges<<<gb_ew, T>>>(E);

    // layer 2: relu(+b1) fused GEMM (+ self-loop init), then edge scatter
    k_gemm64_relu_agg<<<2048, T>>>(W2, b1, n);
    k_agg_edges<<<gb_ew, T>>>(E);

    // A/B projections with relu(+b2) fused on load
    k_gemm64x2_relu<<<2048, T>>>(Wm1, Wm1 + 64 * HID, b2, n);

    // per-edge MLP
    k_edge_mlp<<<4096, T>>>(ea, Wm1, bm1, Wm2, bm2, out, E);
}

// round 9
// speedup vs baseline: 1.2003x; 1.2003x over previous
#include <cuda_runtime.h>

#define HID 64
#define NMAX 100000
#define EMAX 3200000

// ---- scratch (device globals: no allocation allowed; 16B-aligned for vec ops) ----
__device__ __align__(16) float g_dis[NMAX];       // rsqrt(deg)
__device__ __align__(16) float g_f[NMAX * HID];   // pre-aggregation features
__device__ __align__(16) float g_g[NMAX * HID];   // aggregated features
__device__ __align__(16) float g_A[NMAX * HID];   // h2 @ Wm1[0:64]
__device__ __align__(16) float g_B[NMAX * HID];   // h2 @ Wm1[64:128]
__device__ int   g_cnt[NMAX];          // in-degree counts (excl. self-loop)
__device__ int   g_row[NMAX + 1];      // CSR row offsets (by dst)
__device__ int   g_cur[NMAX];          // scatter cursors
__device__ int   g_es[EMAX];           // src index, sorted by dst
__device__ float g_en[EMAX];           // edge norm,  sorted by dst

// ---------------------------------------------------------------------------
__global__ void k_zero_cnt(int n) {
    int i = blockIdx.x * blockDim.x + threadIdx.x;
    if (i < n) g_cnt[i] = 0;
}

__global__ void k_count(const int* __restrict__ ei, int E) {
    int i = blockIdx.x * blockDim.x + threadIdx.x;
    if (i < E) atomicAdd(&g_cnt[ei[E + i]], 1);
}

__global__ void k_rsqrt(int n) {
    int i = blockIdx.x * blockDim.x + threadIdx.x;
    if (i < n) g_dis[i] = rsqrtf((float)g_cnt[i] + 1.0f);  // +1 self-loop
}

// single-block exclusive scan of g_cnt -> g_row/g_cur; g_row[n] = E
__global__ void k_scan(int n) {
    __shared__ int swarp[32];
    __shared__ int s_carry;
    int t = threadIdx.x, lane = t & 31, wid = t >> 5;   // 1024 threads
    if (t == 0) s_carry = 0;
    __syncthreads();
    for (int base = 0; base < n; base += 1024) {
        int i = base + t;
        int v = (i < n) ? g_cnt[i] : 0;
        int incl = v;
#pragma unroll
        for (int o = 1; o < 32; o <<= 1) {
            int y = __shfl_up_sync(0xffffffffu, incl, o);
            if (lane >= o) incl += y;
        }
        if (lane == 31) swarp[wid] = incl;
        __syncthreads();
        if (wid == 0) {
            int wv = swarp[lane];
            int wincl = wv;
#pragma unroll
            for (int o = 1; o < 32; o <<= 1) {
                int y = __shfl_up_sync(0xffffffffu, wincl, o);
                if (lane >= o) wincl += y;
            }
            swarp[lane] = wincl - wv;   // exclusive warp offset
        }
        __syncthreads();
        int carry = s_carry;
        int excl = carry + swarp[wid] + incl - v;
        if (i < n) { g_row[i] = excl; g_cur[i] = excl; }
        __syncthreads();
        if (t == 1023) s_carry = carry + swarp[31] + incl;
        __syncthreads();
    }
    if (t == 0) g_row[n] = s_carry;
}

// scatter (src, norm) into dst buckets
__global__ void k_scatter(const int* __restrict__ ei, int E) {
    int i = blockIdx.x * blockDim.x + threadIdx.x;
    if (i < E) {
        int s = ei[i];
        int d = ei[E + i];
        int pos = atomicAdd(&g_cur[d], 1);
        g_es[pos] = s;
        g_en[pos] = g_dis[s] * g_dis[d];
    }
}

// ---------------------------------------------------------------------------
// g_f = x @ W1   (x: [n,4], W1: [4,64] row-major)
__global__ void k_gemm4(const float* __restrict__ x, const float* __restrict__ W, int n) {
    __shared__ float sW[4 * HID];
    int t = threadIdx.x;
    if (t < 4 * HID) sW[t] = W[t];
    __syncthreads();
    int idx = blockIdx.x * blockDim.x + t;
    if (idx < n * HID) {
        int v = idx >> 6, c = idx & 63;
        float4 xv = ((const float4*)x)[v];
        g_f[idx] = xv.x * sW[c] + xv.y * sW[64 + c] + xv.z * sW[128 + c] + xv.w * sW[192 + c];
    }
}

// ---------------------------------------------------------------------------
// gather-only aggregation, warp per dst node, register accumulator:
//   g_g[v] = g_f[v]*dis[v]^2 + sum_in-edges g_f[src]*norm
__global__ void k_agg_csr(int n) {
    int w = (blockIdx.x * blockDim.x + threadIdx.x) >> 5;
    int lane = threadIdx.x & 31;
    if (w >= n) return;
    int beg = g_row[w], end = g_row[w + 1];
    float dd = g_dis[w]; dd *= dd;
    float2 acc = ((const float2*)(g_f + w * HID))[lane];
    acc.x *= dd; acc.y *= dd;
    int i = beg;
    for (; i + 1 < end; i += 2) {
        int s0 = g_es[i],   s1 = g_es[i + 1];
        float n0 = g_en[i], n1 = g_en[i + 1];
        float2 v0 = ((const float2*)(g_f + s0 * HID))[lane];
        float2 v1 = ((const float2*)(g_f + s1 * HID))[lane];
        acc.x += v0.x * n0; acc.y += v0.y * n0;
        acc.x += v1.x * n1; acc.y += v1.y * n1;
    }
    if (i < end) {
        int s = g_es[i]; float nr = g_en[i];
        float2 v = ((const float2*)(g_f + s * HID))[lane];
        acc.x += v.x * nr; acc.y += v.y * nr;
    }
    ((float2*)(g_g + w * HID))[lane] = acc;
}

// ---------------------------------------------------------------------------
// layer-2 GEMM: g_f = relu(g_g + b1) @ W2   (relu+bias fused on load)
__global__ void k_gemm64_relu(const float* __restrict__ W,
                              const float* __restrict__ bias, int n) {
    __shared__ float sW[HID * HID];
    __shared__ float sx[8][HID];
    __shared__ float sb[HID];
    int t = threadIdx.x;
    for (int i = t; i < HID * HID; i += 256) sW[i] = W[i];
    if (t < HID) sb[t] = bias[t];
    int ty = t >> 5, tx = t & 31;
    for (int base = blockIdx.x * 8; base < n; base += gridDim.x * 8) {
        __syncthreads();
        for (int i = t; i < 8 * HID; i += 256) {
            int r = i >> 6, c = i & 63;
            int v = base + r;
            sx[r][c] = (v < n) ? fmaxf(g_g[v * HID + c] + sb[c], 0.f) : 0.f;
        }
        __syncthreads();
        int v = base + ty;
        if (v < n) {
            float a0 = 0.f, a1 = 0.f;
#pragma unroll
            for (int k = 0; k < HID; k++) {
                float xv = sx[ty][k];
                a0 += xv * sW[k * HID + tx];
                a1 += xv * sW[k * HID + tx + 32];
            }
            g_f[v * HID + tx]      = a0;
            g_f[v * HID + tx + 32] = a1;
        }
    }
}

// ---------------------------------------------------------------------------
// final projections: h2 = relu(g_g + b2) ; g_A = h2 @ WA ; g_B = h2 @ WB
__global__ void k_gemm64x2_relu(const float* __restrict__ WA, const float* __restrict__ WB,
                                const float* __restrict__ bias, int n) {
    __shared__ float sWA[HID * HID];
    __shared__ float sWB[HID * HID];
    __shared__ float sx[8][HID];
    __shared__ float sb[HID];
    int t = threadIdx.x;
    for (int i = t; i < HID * HID; i += 256) { sWA[i] = WA[i]; sWB[i] = WB[i]; }
    if (t < HID) sb[t] = bias[t];
    int ty = t >> 5, tx = t & 31;
    for (int base = blockIdx.x * 8; base < n; base += gridDim.x * 8) {
        __syncthreads();
        for (int i = t; i < 8 * HID; i += 256) {
            int r = i >> 6, c = i & 63;
            int v = base + r;
            sx[r][c] = (v < n) ? fmaxf(g_g[v * HID + c] + sb[c], 0.f) : 0.f;
        }
        __syncthreads();
        int v = base + ty;
        if (v < n) {
            float a0 = 0.f, a1 = 0.f, b0 = 0.f, b1 = 0.f;
#pragma unroll
            for (int k = 0; k < HID; k++) {
                float xv = sx[ty][k];
                a0 += xv * sWA[k * HID + tx];
                a1 += xv * sWA[k * HID + tx + 32];
                b0 += xv * sWB[k * HID + tx];
                b1 += xv * sWB[k * HID + tx + 32];
            }
            g_A[v * HID + tx]      = a0;
            g_A[v * HID + tx + 32] = a1;
            g_B[v * HID + tx]      = b0;
            g_B[v * HID + tx + 32] = b1;
        }
    }
}

// ---------------------------------------------------------------------------
// per-edge MLP, 2 edges/warp, float4 gathers, single float2 store per warp:
// out[e] = relu(A[src] + B[dst] + edge_attr@Wm1c + bm1) @ Wm2 + bm2
__global__ void k_edge_mlp(const int* __restrict__ ei, const float* __restrict__ eattr,
                           const float* __restrict__ Wm1, const float* __restrict__ bm1,
                           const float* __restrict__ Wm2, const float* __restrict__ bm2,
                           float* __restrict__ out, int E) {
    __shared__ float sWc[4 * HID];
    __shared__ float sb[HID];
    __shared__ float sW2[HID];
    __shared__ float sb2;
    int t = threadIdx.x;
    if (t < 4 * HID) sWc[t] = Wm1[128 * HID + t];
    if (t < HID) { sb[t] = bm1[t]; sW2[t] = Wm2[t]; }
    if (t == 0) sb2 = bm2[0];
    __syncthreads();

    int lane = t & 31;
    int half = lane >> 4;
    int l = lane & 15;
    int c0 = l * 4;
    int w = (blockIdx.x * blockDim.x + t) >> 5;
    int nw = (gridDim.x * blockDim.x) >> 5;
    for (int ew = w; ew * 2 < E; ew += nw) {
        int e = ew * 2 + half;
        float p = 0.f;
        if (e < E) {
            int s = ei[e];
            int d = ei[E + e];
            float4 ea = ((const float4*)eattr)[e];
            float4 a = ((const float4*)(g_A + s * HID))[l];
            float4 b = ((const float4*)(g_B + d * HID))[l];
            float za[4] = {a.x + b.x, a.y + b.y, a.z + b.z, a.w + b.w};
#pragma unroll
            for (int j = 0; j < 4; j++) {
                int c = c0 + j;
                float z = za[j] + sb[c]
                        + ea.x * sWc[c] + ea.y * sWc[64 + c]
                        + ea.z * sWc[128 + c] + ea.w * sWc[192 + c];
                p += fmaxf(z, 0.f) * sW2[c];
            }
        }
#pragma unroll
        for (int o = 8; o; o >>= 1) p += __shfl_xor_sync(0xffffffffu, p, o);
        float p1 = __shfl_sync(0xffffffffu, p, 16);
        if (lane == 0) {
            int e0 = ew * 2;
            if (e0 + 1 < E) {
                ((float2*)(out + e0))[0] = make_float2(p + sb2, p1 + sb2);
            } else if (e0 < E) {
                out[e0] = p + sb2;
            }
        }
    }
}

// ---------------------------------------------------------------------------
extern "C" void kernel_launch(void* const* d_in, const int* in_sizes, int n_in,
                              void* d_out, int out_size) {
    const float* x    = (const float*)d_in[0];
    const int*   ei   = (const int*)d_in[1];      // int32 (confirmed)
    const float* ea   = (const float*)d_in[2];
    const float* W1   = (const float*)d_in[3];
    const float* b1   = (const float*)d_in[4];
    const float* W2   = (const float*)d_in[5];
    const float* b2   = (const float*)d_in[6];
    const float* Wm1  = (const float*)d_in[7];
    const float* bm1  = (const float*)d_in[8];
    const float* Wm2  = (const float*)d_in[9];
    const float* bm2  = (const float*)d_in[10];
    float* out = (float*)d_out;

    int n = in_sizes[0] / 4;     // x is [n,4]
    int E = in_sizes[1] / 2;     // edge_index is [2,E]

    const int T = 256;
    int gb_n  = (n + T - 1) / T;
    int gb_nh = (n * HID + T - 1) / T;
    int gb_e  = (E + T - 1) / T;
    int gb_aw = (n * 32 + T - 1) / T;   // warp per node

    // CSR build (per launch; edge list fixed, reused by both layers)
    k_zero_cnt<<<gb_n, T>>>(n);
    k_count<<<gb_e, T>>>(ei, E);
    k_rsqrt<<<gb_n, T>>>(n);
    k_scan<<<1, 1024>>>(n);
    k_scatter<<<gb_e, T>>>(ei, E);

    // layer 1
    k_gemm4<<<gb_nh, T>>>(x, W1, n);
    k_agg_csr<<<gb_aw, T>>>(n);

    // layer 2
    k_gemm64_relu<<<2048, T>>>(W2, b1, n);
    k_agg_csr<<<gb_aw, T>>>(n);

    // A/B projections with relu(+b2) fused on load
    k_gemm64x2_relu<<<2048, T>>>(Wm1, Wm1 + 64 * HID, b2, n);

    // per-edge MLP
    k_edge_mlp<<<4096, T>>>(ei, ea, Wm1, bm1, Wm2, bm2, out, E);
}

// round 10
// speedup vs baseline: 1.3057x; 1.0878x over previous
#include <cuda_runtime.h>

#define HID 64
#define NMAX 100000
#define EMAX 3200000
#define SCAN_B 1024

// ---- scratch (device globals: no allocation allowed; 16B-aligned for vec ops) ----
__device__ __align__(16) float g_dis[NMAX];       // rsqrt(deg)
__device__ __align__(16) float g_f[NMAX * HID];   // pre-aggregation features
__device__ __align__(16) float g_g[NMAX * HID];   // aggregated features
__device__ __align__(16) float g_A[NMAX * HID];   // h2 @ Wm1[0:64]
__device__ __align__(16) float g_B[NMAX * HID];   // h2 @ Wm1[64:128]
__device__ int   g_cnt[NMAX];           // in-degree counts (excl. self-loop)
__device__ int   g_row[NMAX + 1];       // CSR row offsets (by dst)
__device__ int   g_cur[NMAX];           // scatter cursors
__device__ int   g_bsum[(NMAX + SCAN_B - 1) / SCAN_B + 1];  // per-block totals
__device__ int   g_es[EMAX];            // src index, sorted by dst
__device__ float g_en[EMAX];            // edge norm,  sorted by dst

// ---------------------------------------------------------------------------
__global__ void k_zero_cnt(int n) {
    int i = blockIdx.x * blockDim.x + threadIdx.x;
    if (i < n) g_cnt[i] = 0;
}

__global__ void k_count(const int* __restrict__ ei, int E) {
    int i = blockIdx.x * blockDim.x + threadIdx.x;
    if (i < E) atomicAdd(&g_cnt[ei[E + i]], 1);
}

__global__ void k_rsqrt(int n) {
    int i = blockIdx.x * blockDim.x + threadIdx.x;
    if (i < n) g_dis[i] = rsqrtf((float)g_cnt[i] + 1.0f);  // +1 self-loop
}

// phase 1: per-block exclusive scan of g_cnt -> g_row (local), block total -> g_bsum
__global__ void k_scan_blk(int n) {
    __shared__ int swarp[32];
    int t = threadIdx.x, lane = t & 31, wid = t >> 5;
    int i = blockIdx.x * SCAN_B + t;
    int v = (i < n) ? g_cnt[i] : 0;
    int incl = v;
#pragma unroll
    for (int o = 1; o < 32; o <<= 1) {
        int y = __shfl_up_sync(0xffffffffu, incl, o);
        if (lane >= o) incl += y;
    }
    if (lane == 31) swarp[wid] = incl;
    __syncthreads();
    if (wid == 0) {
        int wv = swarp[lane];
        int wincl = wv;
#pragma unroll
        for (int o = 1; o < 32; o <<= 1) {
            int y = __shfl_up_sync(0xffffffffu, wincl, o);
            if (lane >= o) wincl += y;
        }
        swarp[lane] = wincl - wv;   // exclusive warp offset
    }
    __syncthreads();
    int excl = swarp[wid] + incl - v;
    if (i < n) g_row[i] = excl;
    if (t == SCAN_B - 1) g_bsum[blockIdx.x] = excl + v;
}

// phase 2: single small block scans the per-block totals (nb <= 1024) exclusively
__global__ void k_scan_top(int nb) {
    __shared__ int swarp[32];
    int t = threadIdx.x, lane = t & 31, wid = t >> 5;
    int v = (t < nb) ? g_bsum[t] : 0;
    int incl = v;
#pragma unroll
    for (int o = 1; o < 32; o <<= 1) {
        int y = __shfl_up_sync(0xffffffffu, incl, o);
        if (lane >= o) incl += y;
    }
    if (lane == 31) swarp[wid] = incl;
    __syncthreads();
    if (wid == 0) {
        int wv = swarp[lane];
        int wincl = wv;
#pragma unroll
        for (int o = 1; o < 32; o <<= 1) {
            int y = __shfl_up_sync(0xffffffffu, wincl, o);
            if (lane >= o) wincl += y;
        }
        swarp[lane] = wincl - wv;
    }
    __syncthreads();
    if (t < nb) g_bsum[t] = swarp[wid] + incl - v;   // exclusive
}

// phase 3: add block offsets; mirror into g_cur; close the row table
__global__ void k_scan_add(int n, int E) {
    int i = blockIdx.x * blockDim.x + threadIdx.x;
    if (i < n) {
        int r = g_row[i] + g_bsum[i >> 10];
        g_row[i] = r;
        g_cur[i] = r;
    }
    if (i == 0) g_row[n] = E;
}

// scatter (src, norm) into dst buckets
__global__ void k_scatter(const int* __restrict__ ei, int E) {
    int i = blockIdx.x * blockDim.x + threadIdx.x;
    if (i < E) {
        int s = ei[i];
        int d = ei[E + i];
        int pos = atomicAdd(&g_cur[d], 1);
        g_es[pos] = s;
        g_en[pos] = g_dis[s] * g_dis[d];
    }
}

// ---------------------------------------------------------------------------
// g_f = x @ W1   (x: [n,4], W1: [4,64] row-major)
__global__ void k_gemm4(const float* __restrict__ x, const float* __restrict__ W, int n) {
    __shared__ float sW[4 * HID];
    int t = threadIdx.x;
    if (t < 4 * HID) sW[t] = W[t];
    __syncthreads();
    int idx = blockIdx.x * blockDim.x + t;
    if (idx < n * HID) {
        int v = idx >> 6, c = idx & 63;
        float4 xv = ((const float4*)x)[v];
        g_f[idx] = xv.x * sW[c] + xv.y * sW[64 + c] + xv.z * sW[128 + c] + xv.w * sW[192 + c];
    }
}

// ---------------------------------------------------------------------------
// gather-only aggregation, warp per dst node, register accumulator:
//   g_g[v] = g_f[v]*dis[v]^2 + sum_in-edges g_f[src]*norm
__global__ void k_agg_csr(int n) {
    int w = (blockIdx.x * blockDim.x + threadIdx.x) >> 5;
    int lane = threadIdx.x & 31;
    if (w >= n) return;
    int beg = g_row[w], end = g_row[w + 1];
    float dd = g_dis[w]; dd *= dd;
    float2 acc = ((const float2*)(g_f + w * HID))[lane];
    acc.x *= dd; acc.y *= dd;
    int i = beg;
    for (; i + 1 < end; i += 2) {
        int s0 = g_es[i],   s1 = g_es[i + 1];
        float n0 = g_en[i], n1 = g_en[i + 1];
        float2 v0 = ((const float2*)(g_f + s0 * HID))[lane];
        float2 v1 = ((const float2*)(g_f + s1 * HID))[lane];
        acc.x += v0.x * n0; acc.y += v0.y * n0;
        acc.x += v1.x * n1; acc.y += v1.y * n1;
    }
    if (i < end) {
        int s = g_es[i]; float nr = g_en[i];
        float2 v = ((const float2*)(g_f + s * HID))[lane];
        acc.x += v.x * nr; acc.y += v.y * nr;
    }
    ((float2*)(g_g + w * HID))[lane] = acc;
}

// ---------------------------------------------------------------------------
// layer-2 GEMM: g_f = relu(g_g + b1) @ W2   (relu+bias fused on load)
__global__ void k_gemm64_relu(const float* __restrict__ W,
                              const float* __restrict__ bias, int n) {
    __shared__ float sW[HID * HID];
    __shared__ float sx[8][HID];
    __shared__ float sb[HID];
    int t = threadIdx.x;
    for (int i = t; i < HID * HID; i += 256) sW[i] = W[i];
    if (t < HID) sb[t] = bias[t];
    int ty = t >> 5, tx = t & 31;
    for (int base = blockIdx.x * 8; base < n; base += gridDim.x * 8) {
        __syncthreads();
        for (int i = t; i < 8 * HID; i += 256) {
            int r = i >> 6, c = i & 63;
            int v = base + r;
            sx[r][c] = (v < n) ? fmaxf(g_g[v * HID + c] + sb[c], 0.f) : 0.f;
        }
        __syncthreads();
        int v = base + ty;
        if (v < n) {
            float a0 = 0.f, a1 = 0.f;
#pragma unroll
            for (int k = 0; k < HID; k++) {
                float xv = sx[ty][k];
                a0 += xv * sW[k * HID + tx];
                a1 += xv * sW[k * HID + tx + 32];
            }
            g_f[v * HID + tx]      = a0;
            g_f[v * HID + tx + 32] = a1;
        }
    }
}

// ---------------------------------------------------------------------------
// final projections: h2 = relu(g_g + b2) ; g_A = h2 @ WA ; g_B = h2 @ WB
__global__ void k_gemm64x2_relu(const float* __restrict__ WA, const float* __restrict__ WB,
                                const float* __restrict__ bias, int n) {
    __shared__ float sWA[HID * HID];
    __shared__ float sWB[HID * HID];
    __shared__ float sx[8][HID];
    __shared__ float sb[HID];
    int t = threadIdx.x;
    for (int i = t; i < HID * HID; i += 256) { sWA[i] = WA[i]; sWB[i] = WB[i]; }
    if (t < HID) sb[t] = bias[t];
    int ty = t >> 5, tx = t & 31;
    for (int base = blockIdx.x * 8; base < n; base += gridDim.x * 8) {
        __syncthreads();
        for (int i = t; i < 8 * HID; i += 256) {
            int r = i >> 6, c = i & 63;
            int v = base + r;
            sx[r][c] = (v < n) ? fmaxf(g_g[v * HID + c] + sb[c], 0.f) : 0.f;
        }
        __syncthreads();
        int v = base + ty;
        if (v < n) {
            float a0 = 0.f, a1 = 0.f, b0 = 0.f, b1 = 0.f;
#pragma unroll
            for (int k = 0; k < HID; k++) {
                float xv = sx[ty][k];
                a0 += xv * sWA[k * HID + tx];
                a1 += xv * sWA[k * HID + tx + 32];
                b0 += xv * sWB[k * HID + tx];
                b1 += xv * sWB[k * HID + tx + 32];
            }
            g_A[v * HID + tx]      = a0;
            g_A[v * HID + tx + 32] = a1;
            g_B[v * HID + tx]      = b0;
            g_B[v * HID + tx + 32] = b1;
        }
    }
}

// ---------------------------------------------------------------------------
// per-edge MLP, 2 edges/warp, float4 gathers, single float2 store per warp:
// out[e] = relu(A[src] + B[dst] + edge_attr@Wm1c + bm1) @ Wm2 + bm2
__global__ void k_edge_mlp(const int* __restrict__ ei, const float* __restrict__ eattr,
                           const float* __restrict__ Wm1, const float* __restrict__ bm1,
                           const float* __restrict__ Wm2, const float* __restrict__ bm2,
                           float* __restrict__ out, int E) {
    __shared__ float sWc[4 * HID];
    __shared__ float sb[HID];
    __shared__ float sW2[HID];
    __shared__ float sb2;
    int t = threadIdx.x;
    if (t < 4 * HID) sWc[t] = Wm1[128 * HID + t];
    if (t < HID) { sb[t] = bm1[t]; sW2[t] = Wm2[t]; }
    if (t == 0) sb2 = bm2[0];
    __syncthreads();

    int lane = t & 31;
    int half = lane >> 4;
    int l = lane & 15;
    int c0 = l * 4;
    int w = (blockIdx.x * blockDim.x + t) >> 5;
    int nw = (gridDim.x * blockDim.x) >> 5;
    for (int ew = w; ew * 2 < E; ew += nw) {
        int e = ew * 2 + half;
        float p = 0.f;
        if (e < E) {
            int s = ei[e];
            int d = ei[E + e];
            float4 ea = ((const float4*)eattr)[e];
            float4 a = ((const float4*)(g_A + s * HID))[l];
            float4 b = ((const float4*)(g_B + d * HID))[l];
            float za[4] = {a.x + b.x, a.y + b.y, a.z + b.z, a.w + b.w};
#pragma unroll
            for (int j = 0; j < 4; j++) {
                int c = c0 + j;
                float z = za[j] + sb[c]
                        + ea.x * sWc[c] + ea.y * sWc[64 + c]
                        + ea.z * sWc[128 + c] + ea.w * sWc[192 + c];
                p += fmaxf(z, 0.f) * sW2[c];
            }
        }
#pragma unroll
        for (int o = 8; o; o >>= 1) p += __shfl_xor_sync(0xffffffffu, p, o);
        float p1 = __shfl_sync(0xffffffffu, p, 16);
        if (lane == 0) {
            int e0 = ew * 2;
            if (e0 + 1 < E) {
                ((float2*)(out + e0))[0] = make_float2(p + sb2, p1 + sb2);
            } else if (e0 < E) {
                out[e0] = p + sb2;
            }
        }
    }
}

// ---------------------------------------------------------------------------
extern "C" void kernel_launch(void* const* d_in, const int* in_sizes, int n_in,
                              void* d_out, int out_size) {
    const float* x    = (const float*)d_in[0];
    const int*   ei   = (const int*)d_in[1];      // int32 (confirmed)
    const float* ea   = (const float*)d_in[2];
    const float* W1   = (const float*)d_in[3];
    const float* b1   = (const float*)d_in[4];
    const float* W2   = (const float*)d_in[5];
    const float* b2   = (const float*)d_in[6];
    const float* Wm1  = (const float*)d_in[7];
    const float* bm1  = (const float*)d_in[8];
    const float* Wm2  = (const float*)d_in[9];
    const float* bm2  = (const float*)d_in[10];
    float* out = (float*)d_out;

    int n = in_sizes[0] / 4;     // x is [n,4]
    int E = in_sizes[1] / 2;     // edge_index is [2,E]

    const int T = 256;
    int gb_n  = (n + T - 1) / T;
    int gb_nh = (n * HID + T - 1) / T;
    int gb_e  = (E + T - 1) / T;
    int gb_aw = (n * 32 + T - 1) / T;           // warp per node
    int nb    = (n + SCAN_B - 1) / SCAN_B;      // scan blocks (98 for n=100k)

    // CSR build (per launch; edge list fixed, reused by both layers)
    k_zero_cnt<<<gb_n, T>>>(n);
    k_count<<<gb_e, T>>>(ei, E);
    k_rsqrt<<<gb_n, T>>>(n);
    k_scan_blk<<<nb, SCAN_B>>>(n);
    k_scan_top<<<1, 1024>>>(nb);
    k_scan_add<<<gb_n, T>>>(n, E);
    k_scatter<<<gb_e, T>>>(ei, E);

    // layer 1
    k_gemm4<<<gb_nh, T>>>(x, W1, n);
    k_agg_csr<<<gb_aw, T>>>(n);

    // layer 2
    k_gemm64_relu<<<2048, T>>>(W2, b1, n);
    k_agg_csr<<<gb_aw, T>>>(n);

    // A/B projections with relu(+b2) fused on load
    k_gemm64x2_relu<<<2048, T>>>(Wm1, Wm1 + 64 * HID, b2, n);

    // per-edge MLP
    k_edge_mlp<<<4096, T>>>(ei, ea, Wm1, bm1, Wm2, bm2, out, E);
}

// round 12
// speedup vs baseline: 1.3989x; 1.0714x over previous
#include <cuda_runtime.h>

#define HID 64
#define NMAX 100000
#define EMAX 3200000
#define SCAN_B 1024

// ---- scratch (device globals: no allocation allowed; 16B-aligned for vec ops) ----
__device__ __align__(16) float g_dis[NMAX];       // rsqrt(deg)
__device__ __align__(16) float g_f[NMAX * HID];   // pre-aggregation features
__device__ __align__(16) float g_g[NMAX * HID];   // aggregated features
__device__ __align__(16) float g_A[NMAX * HID];   // h2 @ Wm1[0:64]
__device__ __align__(16) float g_B[NMAX * HID];   // h2 @ Wm1[64:128]
__device__ int   g_cnt[NMAX];           // in-degree counts (excl. self-loop)
__device__ int   g_row[NMAX + 1];       // CSR row offsets (by dst)
__device__ int   g_cur[NMAX];           // scatter cursors
__device__ int   g_bsum[(NMAX + SCAN_B - 1) / SCAN_B + 1];  // per-block totals
__device__ int   g_es[EMAX];            // src index, sorted by dst
__device__ int   g_eid[EMAX];           // original edge id, sorted by dst
__device__ float g_en[EMAX];            // edge norm,  sorted by dst

// ---------------------------------------------------------------------------
__global__ void k_zero_cnt(int n) {
    int i = blockIdx.x * blockDim.x + threadIdx.x;
    if (i < n) g_cnt[i] = 0;
}

__global__ void k_count(const int* __restrict__ ei, int E) {
    int i = blockIdx.x * blockDim.x + threadIdx.x;
    if (i < E) atomicAdd(&g_cnt[ei[E + i]], 1);
}

__global__ void k_rsqrt(int n) {
    int i = blockIdx.x * blockDim.x + threadIdx.x;
    if (i < n) g_dis[i] = rsqrtf((float)g_cnt[i] + 1.0f);  // +1 self-loop
}

// phase 1: per-block exclusive scan of g_cnt -> g_row (local), block total -> g_bsum
__global__ void k_scan_blk(int n) {
    __shared__ int swarp[32];
    int t = threadIdx.x, lane = t & 31, wid = t >> 5;
    int i = blockIdx.x * SCAN_B + t;
    int v = (i < n) ? g_cnt[i] : 0;
    int incl = v;
#pragma unroll
    for (int o = 1; o < 32; o <<= 1) {
        int y = __shfl_up_sync(0xffffffffu, incl, o);
        if (lane >= o) incl += y;
    }
    if (lane == 31) swarp[wid] = incl;
    __syncthreads();
    if (wid == 0) {
        int wv = swarp[lane];
        int wincl = wv;
#pragma unroll
        for (int o = 1; o < 32; o <<= 1) {
            int y = __shfl_up_sync(0xffffffffu, wincl, o);
            if (lane >= o) wincl += y;
        }
        swarp[lane] = wincl - wv;   // exclusive warp offset
    }
    __syncthreads();
    int excl = swarp[wid] + incl - v;
    if (i < n) g_row[i] = excl;
    if (t == SCAN_B - 1) g_bsum[blockIdx.x] = excl + v;
}

// phase 2: single small block scans the per-block totals (nb <= 1024) exclusively
__global__ void k_scan_top(int nb) {
    __shared__ int swarp[32];
    int t = threadIdx.x, lane = t & 31, wid = t >> 5;
    int v = (t < nb) ? g_bsum[t] : 0;
    int incl = v;
#pragma unroll
    for (int o = 1; o < 32; o <<= 1) {
        int y = __shfl_up_sync(0xffffffffu, incl, o);
        if (lane >= o) incl += y;
    }
    if (lane == 31) swarp[wid] = incl;
    __syncthreads();
    if (wid == 0) {
        int wv = swarp[lane];
        int wincl = wv;
#pragma unroll
        for (int o = 1; o < 32; o <<= 1) {
            int y = __shfl_up_sync(0xffffffffu, wincl, o);
            if (lane >= o) wincl += y;
        }
        swarp[lane] = wincl - wv;
    }
    __syncthreads();
    if (t < nb) g_bsum[t] = swarp[wid] + incl - v;   // exclusive
}

// phase 3: add block offsets; mirror into g_cur; close the row table
__global__ void k_scan_add(int n, int E) {
    int i = blockIdx.x * blockDim.x + threadIdx.x;
    if (i < n) {
        int r = g_row[i] + g_bsum[i >> 10];
        g_row[i] = r;
        g_cur[i] = r;
    }
    if (i == 0) g_row[n] = E;
}

// scatter (src, norm, edge id) into dst buckets
__global__ void k_scatter(const int* __restrict__ ei, int E) {
    int i = blockIdx.x * blockDim.x + threadIdx.x;
    if (i < E) {
        int s = ei[i];
        int d = ei[E + i];
        int pos = atomicAdd(&g_cur[d], 1);
        g_es[pos]  = s;
        g_eid[pos] = i;
        g_en[pos]  = g_dis[s] * g_dis[d];
    }
}

// ---------------------------------------------------------------------------
// g_f = x @ W1   (x: [n,4], W1: [4,64] row-major)
__global__ void k_gemm4(const float* __restrict__ x, const float* __restrict__ W, int n) {
    __shared__ float sW[4 * HID];
    int t = threadIdx.x;
    if (t < 4 * HID) sW[t] = W[t];
    __syncthreads();
    int idx = blockIdx.x * blockDim.x + t;
    if (idx < n * HID) {
        int v = idx >> 6, c = idx & 63;
        float4 xv = ((const float4*)x)[v];
        g_f[idx] = xv.x * sW[c] + xv.y * sW[64 + c] + xv.z * sW[128 + c] + xv.w * sW[192 + c];
    }
}

// ---------------------------------------------------------------------------
// gather-only aggregation, warp per dst node, register accumulator:
//   g_g[v] = g_f[v]*dis[v]^2 + sum_in-edges g_f[src]*norm
__global__ void k_agg_csr(int n) {
    int w = (blockIdx.x * blockDim.x + threadIdx.x) >> 5;
    int lane = threadIdx.x & 31;
    if (w >= n) return;
    int beg = g_row[w], end = g_row[w + 1];
    float dd = g_dis[w]; dd *= dd;
    float2 acc = ((const float2*)(g_f + w * HID))[lane];
    acc.x *= dd; acc.y *= dd;
    int i = beg;
    for (; i + 1 < end; i += 2) {
        int s0 = g_es[i],   s1 = g_es[i + 1];
        float n0 = g_en[i], n1 = g_en[i + 1];
        float2 v0 = ((const float2*)(g_f + s0 * HID))[lane];
        float2 v1 = ((const float2*)(g_f + s1 * HID))[lane];
        acc.x += v0.x * n0; acc.y += v0.y * n0;
        acc.x += v1.x * n1; acc.y += v1.y * n1;
    }
    if (i < end) {
        int s = g_es[i]; float nr = g_en[i];
        float2 v = ((const float2*)(g_f + s * HID))[lane];
        acc.x += v.x * nr; acc.y += v.y * nr;
    }
    ((float2*)(g_g + w * HID))[lane] = acc;
}

// ---------------------------------------------------------------------------
// layer-2 GEMM: g_f = relu(g_g + b1) @ W2   (relu+bias fused on load)
__global__ void k_gemm64_relu(const float* __restrict__ W,
                              const float* __restrict__ bias, int n) {
    __shared__ float sW[HID * HID];
    __shared__ float sx[8][HID];
    __shared__ float sb[HID];
    int t = threadIdx.x;
    for (int i = t; i < HID * HID; i += 256) sW[i] = W[i];
    if (t < HID) sb[t] = bias[t];
    int ty = t >> 5, tx = t & 31;
    for (int base = blockIdx.x * 8; base < n; base += gridDim.x * 8) {
        __syncthreads();
        for (int i = t; i < 8 * HID; i += 256) {
            int r = i >> 6, c = i & 63;
            int v = base + r;
            sx[r][c] = (v < n) ? fmaxf(g_g[v * HID + c] + sb[c], 0.f) : 0.f;
        }
        __syncthreads();
        int v = base + ty;
        if (v < n) {
            float a0 = 0.f, a1 = 0.f;
#pragma unroll
            for (int k = 0; k < HID; k++) {
                float xv = sx[ty][k];
                a0 += xv * sW[k * HID + tx];
                a1 += xv * sW[k * HID + tx + 32];
            }
            g_f[v * HID + tx]      = a0;
            g_f[v * HID + tx + 32] = a1;
        }
    }
}

// ---------------------------------------------------------------------------
// final projections: h2 = relu(g_g + b2) ; g_A = h2 @ WA ; g_B = h2 @ WB
__global__ void k_gemm64x2_relu(const float* __restrict__ WA, const float* __restrict__ WB,
                                const float* __restrict__ bias, int n) {
    __shared__ float sWA[HID * HID];
    __shared__ float sWB[HID * HID];
    __shared__ float sx[8][HID];
    __shared__ float sb[HID];
    int t = threadIdx.x;
    for (int i = t; i < HID * HID; i += 256) { sWA[i] = WA[i]; sWB[i] = WB[i]; }
    if (t < HID) sb[t] = bias[t];
    int ty = t >> 5, tx = t & 31;
    for (int base = blockIdx.x * 8; base < n; base += gridDim.x * 8) {
        __syncthreads();
        for (int i = t; i < 8 * HID; i += 256) {
            int r = i >> 6, c = i & 63;
            int v = base + r;
            sx[r][c] = (v < n) ? fmaxf(g_g[v * HID + c] + sb[c], 0.f) : 0.f;
        }
        __syncthreads();
        int v = base + ty;
        if (v < n) {
            float a0 = 0.f, a1 = 0.f, b0 = 0.f, b1 = 0.f;
#pragma unroll
            for (int k = 0; k < HID; k++) {
                float xv = sx[ty][k];
                a0 += xv * sWA[k * HID + tx];
                a1 += xv * sWA[k * HID + tx + 32];
                b0 += xv * sWB[k * HID + tx];
                b1 += xv * sWB[k * HID + tx + 32];
            }
            g_A[v * HID + tx]      = a0;
            g_A[v * HID + tx + 32] = a1;
            g_B[v * HID + tx]      = b0;
            g_B[v * HID + tx + 32] = b1;
        }
    }
}

// ---------------------------------------------------------------------------
// per-edge MLP over CSR order: warp per dst row, B[dst] loaded ONCE per row.
// out[eid] = relu(A[src] + B[dst] + edge_attr[eid]@Wm1c + bm1) @ Wm2 + bm2
__global__ void k_edge_mlp_csr(const float* __restrict__ eattr,
                               const float* __restrict__ Wm1, const float* __restrict__ bm1,
                               const float* __restrict__ Wm2, const float* __restrict__ bm2,
                               float* __restrict__ out, int n) {
    __shared__ float sWc[4 * HID];
    __shared__ float sb[HID];
    __shared__ float sW2[HID];
    __shared__ float sb2;
    int t = threadIdx.x;
    if (t < 4 * HID) sWc[t] = Wm1[128 * HID + t];
    if (t < HID) { sb[t] = bm1[t]; sW2[t] = Wm2[t]; }
    if (t == 0) sb2 = bm2[0];
    __syncthreads();

    int w = (blockIdx.x * blockDim.x + t) >> 5;   // dst node
    if (w >= n) return;
    int lane = t & 31;
    int half = lane >> 4;
    int l = lane & 15;
    int c0 = l * 4;
    int beg = g_row[w], end = g_row[w + 1];
    if (beg == end) return;

    // per-row constants: B[dst] + bias, and Wm2 slice
    float4 b = ((const float4*)(g_B + w * HID))[l];
    float base0 = b.x + sb[c0],     base1 = b.y + sb[c0 + 1];
    float base2 = b.z + sb[c0 + 2], base3 = b.w + sb[c0 + 3];
    float w20 = sW2[c0], w21 = sW2[c0 + 1], w22 = sW2[c0 + 2], w23 = sW2[c0 + 3];

    for (int i = beg; i < end; i += 2) {
        int idx = i + half;
        float p = 0.f;
        int eid = 0;
        if (idx < end) {
            int s = g_es[idx];
            eid = g_eid[idx];
            float4 ea = ((const float4*)eattr)[eid];
            float4 a = ((const float4*)(g_A + s * HID))[l];
            float z0 = a.x + base0 + ea.x * sWc[c0]     + ea.y * sWc[64 + c0]
                                   + ea.z * sWc[128 + c0]     + ea.w * sWc[192 + c0];
            float z1 = a.y + base1 + ea.x * sWc[c0 + 1] + ea.y * sWc[64 + c0 + 1]
                                   + ea.z * sWc[128 + c0 + 1] + ea.w * sWc[192 + c0 + 1];
            float z2 = a.z + base2 + ea.x * sWc[c0 + 2] + ea.y * sWc[64 + c0 + 2]
                                   + ea.z * sWc[128 + c0 + 2] + ea.w * sWc[192 + c0 + 2];
            float z3 = a.w + base3 + ea.x * sWc[c0 + 3] + ea.y * sWc[64 + c0 + 3]
                                   + ea.z * sWc[128 + c0 + 3] + ea.w * sWc[192 + c0 + 3];
            p = fmaxf(z0, 0.f) * w20 + fmaxf(z1, 0.f) * w21
              + fmaxf(z2, 0.f) * w22 + fmaxf(z3, 0.f) * w23;
        }
        // reduce over the 16 lanes of each half-warp
#pragma unroll
        for (int o = 8; o; o >>= 1) p += __shfl_xor_sync(0xffffffffu, p, o);
        float p1  = __shfl_sync(0xffffffffu, p, 16);
        int eid1  = __shfl_sync(0xffffffffu, eid, 16);
        if (lane == 0) {
            out[eid] = p + sb2;
            if (i + 1 < end) out[eid1] = p1 + sb2;
        }
    }
}

// ---------------------------------------------------------------------------
extern "C" void kernel_launch(void* const* d_in, const int* in_sizes, int n_in,
                              void* d_out, int out_size) {
    const float* x    = (const float*)d_in[0];
    const int*   ei   = (const int*)d_in[1];      // int32 (confirmed)
    const float* ea   = (const float*)d_in[2];
    const float* W1   = (const float*)d_in[3];
    const float* b1   = (const float*)d_in[4];
    const float* W2   = (const float*)d_in[5];
    const float* b2   = (const float*)d_in[6];
    const float* Wm1  = (const float*)d_in[7];
    const float* bm1  = (const float*)d_in[8];
    const float* Wm2  = (const float*)d_in[9];
    const float* bm2  = (const float*)d_in[10];
    float* out = (float*)d_out;

    int n = in_sizes[0] / 4;     // x is [n,4]
    int E = in_sizes[1] / 2;     // edge_index is [2,E]

    const int T = 256;
    int gb_n  = (n + T - 1) / T;
    int gb_nh = (n * HID + T - 1) / T;
    int gb_e  = (E + T - 1) / T;
    int gb_aw = (n * 32 + T - 1) / T;           // warp per node
    int nb    = (n + SCAN_B - 1) / SCAN_B;      // scan blocks (98 for n=100k)

    // CSR build (per launch; edge list fixed, reused by both layers + edge MLP)
    k_zero_cnt<<<gb_n, T>>>(n);
    k_count<<<gb_e, T>>>(ei, E);
    k_rsqrt<<<gb_n, T>>>(n);
    k_scan_blk<<<nb, SCAN_B>>>(n);
    k_scan_top<<<1, 1024>>>(nb);
    k_scan_add<<<gb_n, T>>>(n, E);
    k_scatter<<<gb_e, T>>>(ei, E);

    // layer 1
    k_gemm4<<<gb_nh, T>>>(x, W1, n);
    k_agg_csr<<<gb_aw, T>>>(n);

    // layer 2
    k_gemm64_relu<<<2048, T>>>(W2, b1, n);
    k_agg_csr<<<gb_aw, T>>>(n);

    // A/B projections with relu(+b2) fused on load
    k_gemm64x2_relu<<<2048, T>>>(Wm1, Wm1 + 64 * HID, b2, n);

    // per-edge MLP over CSR order (B[dst] amortized per row)
    k_edge_mlp_csr<<<gb_aw, T>>>(ea, Wm1, bm1, Wm2, bm2, out, n);
}

// round 13
// speedup vs baseline: 1.4109x; 1.0085x over previous
#include <cuda_runtime.h>

#define HID 64
#define NMAX 100000
#define EMAX 3200000
#define SCAN_B 1024

// ---- scratch (device globals: no allocation allowed; 16B-aligned for vec ops) ----
__device__ __align__(16) float g_dis[NMAX];       // rsqrt(deg)
__device__ __align__(16) float g_f[NMAX * HID];   // pre-aggregation features
__device__ __align__(16) float g_g[NMAX * HID];   // aggregated features
__device__ __align__(16) float g_A[NMAX * HID];   // h2 @ Wm1[0:64]
__device__ __align__(16) float g_B[NMAX * HID];   // h2 @ Wm1[64:128]
__device__ int   g_cnt[NMAX];           // in-degree counts (excl. self-loop)
__device__ int   g_row[NMAX + 1];       // CSR row offsets (by dst)
__device__ int   g_cur[NMAX];           // scatter cursors
__device__ int   g_bsum[(NMAX + SCAN_B - 1) / SCAN_B + 1];  // per-block totals
__device__ int   g_es[EMAX];            // src index, sorted by dst
__device__ int   g_eid[EMAX];           // original edge id, sorted by dst
__device__ float g_en[EMAX];            // edge norm,  sorted by dst

// ---------------------------------------------------------------------------
__global__ void k_zero_cnt(int n) {
    int i = blockIdx.x * blockDim.x + threadIdx.x;
    if (i < n) g_cnt[i] = 0;
}

__global__ void k_count(const int* __restrict__ ei, int E) {
    int i = blockIdx.x * blockDim.x + threadIdx.x;
    if (i < E) atomicAdd(&g_cnt[ei[E + i]], 1);
}

__global__ void k_rsqrt(int n) {
    int i = blockIdx.x * blockDim.x + threadIdx.x;
    if (i < n) g_dis[i] = rsqrtf((float)g_cnt[i] + 1.0f);  // +1 self-loop
}

// phase 1: per-block exclusive scan of g_cnt -> g_row (local), block total -> g_bsum
__global__ void k_scan_blk(int n) {
    __shared__ int swarp[32];
    int t = threadIdx.x, lane = t & 31, wid = t >> 5;
    int i = blockIdx.x * SCAN_B + t;
    int v = (i < n) ? g_cnt[i] : 0;
    int incl = v;
#pragma unroll
    for (int o = 1; o < 32; o <<= 1) {
        int y = __shfl_up_sync(0xffffffffu, incl, o);
        if (lane >= o) incl += y;
    }
    if (lane == 31) swarp[wid] = incl;
    __syncthreads();
    if (wid == 0) {
        int wv = swarp[lane];
        int wincl = wv;
#pragma unroll
        for (int o = 1; o < 32; o <<= 1) {
            int y = __shfl_up_sync(0xffffffffu, wincl, o);
            if (lane >= o) wincl += y;
        }
        swarp[lane] = wincl - wv;   // exclusive warp offset
    }
    __syncthreads();
    int excl = swarp[wid] + incl - v;
    if (i < n) g_row[i] = excl;
    if (t == SCAN_B - 1) g_bsum[blockIdx.x] = excl + v;
}

// phase 2: single small block scans the per-block totals (nb <= 1024) exclusively
__global__ void k_scan_top(int nb) {
    __shared__ int swarp[32];
    int t = threadIdx.x, lane = t & 31, wid = t >> 5;
    int v = (t < nb) ? g_bsum[t] : 0;
    int incl = v;
#pragma unroll
    for (int o = 1; o < 32; o <<= 1) {
        int y = __shfl_up_sync(0xffffffffu, incl, o);
        if (lane >= o) incl += y;
    }
    if (lane == 31) swarp[wid] = incl;
    __syncthreads();
    if (wid == 0) {
        int wv = swarp[lane];
        int wincl = wv;
#pragma unroll
        for (int o = 1; o < 32; o <<= 1) {
            int y = __shfl_up_sync(0xffffffffu, wincl, o);
            if (lane >= o) wincl += y;
        }
        swarp[lane] = wincl - wv;
    }
    __syncthreads();
    if (t < nb) g_bsum[t] = swarp[wid] + incl - v;   // exclusive
}

// phase 3: add block offsets; mirror into g_cur; close the row table
__global__ void k_scan_add(int n, int E) {
    int i = blockIdx.x * blockDim.x + threadIdx.x;
    if (i < n) {
        int r = g_row[i] + g_bsum[i >> 10];
        g_row[i] = r;
        g_cur[i] = r;
    }
    if (i == 0) g_row[n] = E;
}

// scatter (src, norm, edge id) into dst buckets
__global__ void k_scatter(const int* __restrict__ ei, int E) {
    int i = blockIdx.x * blockDim.x + threadIdx.x;
    if (i < E) {
        int s = ei[i];
        int d = ei[E + i];
        int pos = atomicAdd(&g_cur[d], 1);
        g_es[pos]  = s;
        g_eid[pos] = i;
        g_en[pos]  = g_dis[s] * g_dis[d];
    }
}

// ---------------------------------------------------------------------------
// g_f = x @ W1   (x: [n,4], W1: [4,64] row-major)
__global__ void k_gemm4(const float* __restrict__ x, const float* __restrict__ W, int n) {
    __shared__ float sW[4 * HID];
    int t = threadIdx.x;
    if (t < 4 * HID) sW[t] = W[t];
    __syncthreads();
    int idx = blockIdx.x * blockDim.x + t;
    if (idx < n * HID) {
        int v = idx >> 6, c = idx & 63;
        float4 xv = ((const float4*)x)[v];
        g_f[idx] = xv.x * sW[c] + xv.y * sW[64 + c] + xv.z * sW[128 + c] + xv.w * sW[192 + c];
    }
}

// ---------------------------------------------------------------------------
// gather-only aggregation, warp per dst node. Two 16-lane halves each own
// alternating edges (float4/lane = full 256B row per half), unrolled x2:
// 4 independent row-loads in flight per warp.
//   g_g[v] = g_f[v]*dis[v]^2 + sum_in-edges g_f[src]*norm
__global__ void k_agg_csr(int n) {
    int w = (blockIdx.x * blockDim.x + threadIdx.x) >> 5;
    int lane = threadIdx.x & 31;
    if (w >= n) return;
    int half = lane >> 4;
    int l = lane & 15;
    int beg = g_row[w], end = g_row[w + 1];
    float dd = g_dis[w]; dd *= dd;

    float4 acc = make_float4(0.f, 0.f, 0.f, 0.f);
    if (half == 0) {
        float4 s = ((const float4*)(g_f + w * HID))[l];
        acc.x = s.x * dd; acc.y = s.y * dd; acc.z = s.z * dd; acc.w = s.w * dd;
    }

    int i = beg + half;
    // unrolled x2 per half: edges i and i+2
    for (; i + 2 < end; i += 4) {
        int s0 = g_es[i],     s1 = g_es[i + 2];
        float n0 = g_en[i],   n1 = g_en[i + 2];
        float4 v0 = ((const float4*)(g_f + s0 * HID))[l];
        float4 v1 = ((const float4*)(g_f + s1 * HID))[l];
        acc.x += v0.x * n0 + v1.x * n1;
        acc.y += v0.y * n0 + v1.y * n1;
        acc.z += v0.z * n0 + v1.z * n1;
        acc.w += v0.w * n0 + v1.w * n1;
    }
    if (i < end) {
        int s = g_es[i]; float nr = g_en[i];
        float4 v = ((const float4*)(g_f + s * HID))[l];
        acc.x += v.x * nr; acc.y += v.y * nr; acc.z += v.z * nr; acc.w += v.w * nr;
    }

    // combine the two halves (channel c lives on lanes l and l+16)
    acc.x += __shfl_down_sync(0xffffffffu, acc.x, 16);
    acc.y += __shfl_down_sync(0xffffffffu, acc.y, 16);
    acc.z += __shfl_down_sync(0xffffffffu, acc.z, 16);
    acc.w += __shfl_down_sync(0xffffffffu, acc.w, 16);
    if (half == 0) ((float4*)(g_g + w * HID))[l] = acc;
}

// ---------------------------------------------------------------------------
// layer-2 GEMM: g_f = relu(g_g + b1) @ W2   (relu+bias fused on load)
__global__ void k_gemm64_relu(const float* __restrict__ W,
                              const float* __restrict__ bias, int n) {
    __shared__ float sW[HID * HID];
    __shared__ float sx[8][HID];
    __shared__ float sb[HID];
    int t = threadIdx.x;
    for (int i = t; i < HID * HID; i += 256) sW[i] = W[i];
    if (t < HID) sb[t] = bias[t];
    int ty = t >> 5, tx = t & 31;
    for (int base = blockIdx.x * 8; base < n; base += gridDim.x * 8) {
        __syncthreads();
        for (int i = t; i < 8 * HID; i += 256) {
            int r = i >> 6, c = i & 63;
            int v = base + r;
            sx[r][c] = (v < n) ? fmaxf(g_g[v * HID + c] + sb[c], 0.f) : 0.f;
        }
        __syncthreads();
        int v = base + ty;
        if (v < n) {
            float a0 = 0.f, a1 = 0.f;
#pragma unroll
            for (int k = 0; k < HID; k++) {
                float xv = sx[ty][k];
                a0 += xv * sW[k * HID + tx];
                a1 += xv * sW[k * HID + tx + 32];
            }
            g_f[v * HID + tx]      = a0;
            g_f[v * HID + tx + 32] = a1;
        }
    }
}

// ---------------------------------------------------------------------------
// final projections: h2 = relu(g_g + b2) ; g_A = h2 @ WA ; g_B = h2 @ WB
__global__ void k_gemm64x2_relu(const float* __restrict__ WA, const float* __restrict__ WB,
                                const float* __restrict__ bias, int n) {
    __shared__ float sWA[HID * HID];
    __shared__ float sWB[HID * HID];
    __shared__ float sx[8][HID];
    __shared__ float sb[HID];
    int t = threadIdx.x;
    for (int i = t; i < HID * HID; i += 256) { sWA[i] = WA[i]; sWB[i] = WB[i]; }
    if (t < HID) sb[t] = bias[t];
    int ty = t >> 5, tx = t & 31;
    for (int base = blockIdx.x * 8; base < n; base += gridDim.x * 8) {
        __syncthreads();
        for (int i = t; i < 8 * HID; i += 256) {
            int r = i >> 6, c = i & 63;
            int v = base + r;
            sx[r][c] = (v < n) ? fmaxf(g_g[v * HID + c] + sb[c], 0.f) : 0.f;
        }
        __syncthreads();
        int v = base + ty;
        if (v < n) {
            float a0 = 0.f, a1 = 0.f, b0 = 0.f, b1 = 0.f;
#pragma unroll
            for (int k = 0; k < HID; k++) {
                float xv = sx[ty][k];
                a0 += xv * sWA[k * HID + tx];
                a1 += xv * sWA[k * HID + tx + 32];
                b0 += xv * sWB[k * HID + tx];
                b1 += xv * sWB[k * HID + tx + 32];
            }
            g_A[v * HID + tx]      = a0;
            g_A[v * HID + tx + 32] = a1;
            g_B[v * HID + tx]      = b0;
            g_B[v * HID + tx + 32] = b1;
        }
    }
}

// ---------------------------------------------------------------------------
// per-edge MLP over CSR order: warp per dst row, B[dst] once per row,
// unrolled x2 (4 edges / 4 A-row loads in flight per warp).
// out[eid] = relu(A[src] + B[dst] + edge_attr[eid]@Wm1c + bm1) @ Wm2 + bm2
__global__ void k_edge_mlp_csr(const float* __restrict__ eattr,
                               const float* __restrict__ Wm1, const float* __restrict__ bm1,
                               const float* __restrict__ Wm2, const float* __restrict__ bm2,
                               float* __restrict__ out, int n) {
    __shared__ float sWc[4 * HID];
    __shared__ float sb[HID];
    __shared__ float sW2[HID];
    __shared__ float sb2;
    int t = threadIdx.x;
    if (t < 4 * HID) sWc[t] = Wm1[128 * HID + t];
    if (t < HID) { sb[t] = bm1[t]; sW2[t] = Wm2[t]; }
    if (t == 0) sb2 = bm2[0];
    __syncthreads();

    int w = (blockIdx.x * blockDim.x + t) >> 5;   // dst node
    if (w >= n) return;
    int lane = t & 31;
    int half = lane >> 4;
    int l = lane & 15;
    int c0 = l * 4;
    int beg = g_row[w], end = g_row[w + 1];
    if (beg == end) return;

    // per-row constants: B[dst] + bias, and Wm2 slice
    float4 b = ((const float4*)(g_B + w * HID))[l];
    float base0 = b.x + sb[c0],     base1 = b.y + sb[c0 + 1];
    float base2 = b.z + sb[c0 + 2], base3 = b.w + sb[c0 + 3];
    float w20 = sW2[c0], w21 = sW2[c0 + 1], w22 = sW2[c0 + 2], w23 = sW2[c0 + 3];
    float wc00 = sWc[c0],       wc01 = sWc[c0 + 1],       wc02 = sWc[c0 + 2],       wc03 = sWc[c0 + 3];
    float wc10 = sWc[64 + c0],  wc11 = sWc[64 + c0 + 1],  wc12 = sWc[64 + c0 + 2],  wc13 = sWc[64 + c0 + 3];
    float wc20 = sWc[128 + c0], wc21 = sWc[128 + c0 + 1], wc22 = sWc[128 + c0 + 2], wc23 = sWc[128 + c0 + 3];
    float wc30 = sWc[192 + c0], wc31 = sWc[192 + c0 + 1], wc32 = sWc[192 + c0 + 2], wc33 = sWc[192 + c0 + 3];

    for (int i = beg; i < end; i += 4) {
        int idx0 = i + half;
        int idx1 = i + 2 + half;
        float p0 = 0.f, p1 = 0.f;
        int eid0 = 0, eid1 = 0;
        bool v0 = idx0 < end, v1 = idx1 < end;
        int s0 = 0, s1 = 0;
        if (v0) { s0 = g_es[idx0]; eid0 = g_eid[idx0]; }
        if (v1) { s1 = g_es[idx1]; eid1 = g_eid[idx1]; }
        float4 ea0 = v0 ? ((const float4*)eattr)[eid0] : make_float4(0,0,0,0);
        float4 ea1 = v1 ? ((const float4*)eattr)[eid1] : make_float4(0,0,0,0);
        float4 a0 = v0 ? ((const float4*)(g_A + s0 * HID))[l] : make_float4(0,0,0,0);
        float4 a1 = v1 ? ((const float4*)(g_A + s1 * HID))[l] : make_float4(0,0,0,0);
        if (v0) {
            float z0 = a0.x + base0 + ea0.x * wc00 + ea0.y * wc10 + ea0.z * wc20 + ea0.w * wc30;
            float z1 = a0.y + base1 + ea0.x * wc01 + ea0.y * wc11 + ea0.z * wc21 + ea0.w * wc31;
            float z2 = a0.z + base2 + ea0.x * wc02 + ea0.y * wc12 + ea0.z * wc22 + ea0.w * wc32;
            float z3 = a0.w + base3 + ea0.x * wc03 + ea0.y * wc13 + ea0.z * wc23 + ea0.w * wc33;
            p0 = fmaxf(z0, 0.f) * w20 + fmaxf(z1, 0.f) * w21
               + fmaxf(z2, 0.f) * w22 + fmaxf(z3, 0.f) * w23;
        }
        if (v1) {
            float z0 = a1.x + base0 + ea1.x * wc00 + ea1.y * wc10 + ea1.z * wc20 + ea1.w * wc30;
            float z1 = a1.y + base1 + ea1.x * wc01 + ea1.y * wc11 + ea1.z * wc21 + ea1.w * wc31;
            float z2 = a1.z + base2 + ea1.x * wc02 + ea1.y * wc12 + ea1.z * wc22 + ea1.w * wc32;
            float z3 = a1.w + base3 + ea1.x * wc03 + ea1.y * wc13 + ea1.z * wc23 + ea1.w * wc33;
            p1 = fmaxf(z0, 0.f) * w20 + fmaxf(z1, 0.f) * w21
               + fmaxf(z2, 0.f) * w22 + fmaxf(z3, 0.f) * w23;
        }
        // two independent 16-lane reductions (interleaved shuffles)
#pragma unroll
        for (int o = 8; o; o >>= 1) {
            p0 += __shfl_xor_sync(0xffffffffu, p0, o);
            p1 += __shfl_xor_sync(0xffffffffu, p1, o);
        }
        float p0h = __shfl_sync(0xffffffffu, p0, 16);
        float p1h = __shfl_sync(0xffffffffu, p1, 16);
        int e0h = __shfl_sync(0xffffffffu, eid0, 16);
        int e1h = __shfl_sync(0xffffffffu, eid1, 16);
        if (lane == 0) {
            out[eid0] = p0 + sb2;                       // idx = i   (always valid)
            if (i + 1 < end) out[e0h] = p0h + sb2;      // idx = i+1
            if (i + 2 < end) out[eid1] = p1 + sb2;      // idx = i+2
            if (i + 3 < end) out[e1h] = p1h + sb2;      // idx = i+3
        }
    }
}

// ---------------------------------------------------------------------------
extern "C" void kernel_launch(void* const* d_in, const int* in_sizes, int n_in,
                              void* d_out, int out_size) {
    const float* x    = (const float*)d_in[0];
    const int*   ei   = (const int*)d_in[1];      // int32 (confirmed)
    const float* ea   = (const float*)d_in[2];
    const float* W1   = (const float*)d_in[3];
    const float* b1   = (const float*)d_in[4];
    const float* W2   = (const float*)d_in[5];
    const float* b2   = (const float*)d_in[6];
    const float* Wm1  = (const float*)d_in[7];
    const float* bm1  = (const float*)d_in[8];
    const float* Wm2  = (const float*)d_in[9];
    const float* bm2  = (const float*)d_in[10];
    float* out = (float*)d_out;

    int n = in_sizes[0] / 4;     // x is [n,4]
    int E = in_sizes[1] / 2;     // edge_index is [2,E]

    const int T = 256;
    int gb_n  = (n + T - 1) / T;
    int gb_nh = (n * HID + T - 1) / T;
    int gb_e  = (E + T - 1) / T;
    int gb_aw = (n * 32 + T - 1) / T;           // warp per node
    int nb    = (n + SCAN_B - 1) / SCAN_B;      // scan blocks (98 for n=100k)

    // CSR build (per launch; edge list fixed, reused by both layers + edge MLP)
    k_zero_cnt<<<gb_n, T>>>(n);
    k_count<<<gb_e, T>>>(ei, E);
    k_rsqrt<<<gb_n, T>>>(n);
    k_scan_blk<<<nb, SCAN_B>>>(n);
    k_scan_top<<<1, 1024>>>(nb);
    k_scan_add<<<gb_n, T>>>(n, E);
    k_scatter<<<gb_e, T>>>(ei, E);

    // layer 1
    k_gemm4<<<gb_nh, T>>>(x, W1, n);
    k_agg_csr<<<gb_aw, T>>>(n);

    // layer 2
    k_gemm64_relu<<<2048, T>>>(W2, b1, n);
    k_agg_csr<<<gb_aw, T>>>(n);

    // A/B projections with relu(+b2) fused on load
    k_gemm64x2_relu<<<2048, T>>>(Wm1, Wm1 + 64 * HID, b2, n);

    // per-edge MLP over CSR order (B[dst] amortized per row, 4 edges in flight)
    k_edge_mlp_csr<<<gb_aw, T>>>(ea, Wm1, bm1, Wm2, bm2, out, n);
}

// round 16
// speedup vs baseline: 1.6874x; 1.1960x over previous
#include <cuda_runtime.h>
#include <cuda_fp16.h>

#define HID 64
#define NMAX 100000
#define EMAX 3200000
#define SCAN_B 1024

// ---- scratch (device globals; 16B-aligned for vec ops) ----
__device__ __align__(16) float  g_dis[NMAX];        // rsqrt(deg)
__device__ __align__(16) __half g_fh[NMAX * HID];   // pre-aggregation features (fp16)
__device__ __align__(16) float  g_g[NMAX * HID];    // aggregated features (fp32)
__device__ __align__(16) __half g_Ah[NMAX * HID];   // h2 @ Wm1[0:64]  (fp16, gathered)
__device__ __align__(16) float  g_B[NMAX * HID];    // h2 @ Wm1[64:128] (fp32, amortized)
__device__ int   g_cnt[NMAX];
__device__ int   g_row[NMAX + 1];
__device__ int   g_cur[NMAX];
__device__ int   g_bsum[(NMAX + SCAN_B - 1) / SCAN_B + 1];
__device__ int   g_es[EMAX];            // src index, sorted by dst
__device__ int   g_eid[EMAX];           // original edge id, sorted by dst
__device__ float g_en[EMAX];            // edge norm,  sorted by dst

// ---------------------------------------------------------------------------
__global__ void k_zero_cnt(int n) {
    int i = blockIdx.x * blockDim.x + threadIdx.x;
    if (i < n) g_cnt[i] = 0;
}

__global__ void k_count(const int* __restrict__ ei, int E) {
    int i = blockIdx.x * blockDim.x + threadIdx.x;
    if (i < E) atomicAdd(&g_cnt[ei[E + i]], 1);
}

__global__ void k_rsqrt(int n) {
    int i = blockIdx.x * blockDim.x + threadIdx.x;
    if (i < n) g_dis[i] = rsqrtf((float)g_cnt[i] + 1.0f);  // +1 self-loop
}

__global__ void k_scan_blk(int n) {
    __shared__ int swarp[32];
    int t = threadIdx.x, lane = t & 31, wid = t >> 5;
    int i = blockIdx.x * SCAN_B + t;
    int v = (i < n) ? g_cnt[i] : 0;
    int incl = v;
#pragma unroll
    for (int o = 1; o < 32; o <<= 1) {
        int y = __shfl_up_sync(0xffffffffu, incl, o);
        if (lane >= o) incl += y;
    }
    if (lane == 31) swarp[wid] = incl;
    __syncthreads();
    if (wid == 0) {
        int wv = swarp[lane];
        int wincl = wv;
#pragma unroll
        for (int o = 1; o < 32; o <<= 1) {
            int y = __shfl_up_sync(0xffffffffu, wincl, o);
            if (lane >= o) wincl += y;
        }
        swarp[lane] = wincl - wv;
    }
    __syncthreads();
    int excl = swarp[wid] + incl - v;
    if (i < n) g_row[i] = excl;
    if (t == SCAN_B - 1) g_bsum[blockIdx.x] = excl + v;
}

__global__ void k_scan_top(int nb) {
    __shared__ int swarp[32];
    int t = threadIdx.x, lane = t & 31, wid = t >> 5;
    int v = (t < nb) ? g_bsum[t] : 0;
    int incl = v;
#pragma unroll
    for (int o = 1; o < 32; o <<= 1) {
        int y = __shfl_up_sync(0xffffffffu, incl, o);
        if (lane >= o) incl += y;
    }
    if (lane == 31) swarp[wid] = incl;
    __syncthreads();
    if (wid == 0) {
        int wv = swarp[lane];
        int wincl = wv;
#pragma unroll
        for (int o = 1; o < 32; o <<= 1) {
            int y = __shfl_up_sync(0xffffffffu, wincl, o);
            if (lane >= o) wincl += y;
        }
        swarp[lane] = wincl - wv;
    }
    __syncthreads();
    if (t < nb) g_bsum[t] = swarp[wid] + incl - v;
}

__global__ void k_scan_add(int n, int E) {
    int i = blockIdx.x * blockDim.x + threadIdx.x;
    if (i < n) {
        int r = g_row[i] + g_bsum[i >> 10];
        g_row[i] = r;
        g_cur[i] = r;
    }
    if (i == 0) g_row[n] = E;
}

__global__ void k_scatter(const int* __restrict__ ei, int E) {
    int i = blockIdx.x * blockDim.x + threadIdx.x;
    if (i < E) {
        int s = ei[i];
        int d = ei[E + i];
        int pos = atomicAdd(&g_cur[d], 1);
        g_es[pos]  = s;
        g_eid[pos] = i;
        g_en[pos]  = g_dis[s] * g_dis[d];
    }
}

// ---------------------------------------------------------------------------
// g_fh = half(x @ W1)
__global__ void k_gemm4(const float* __restrict__ x, const float* __restrict__ W, int n) {
    __shared__ float sW[4 * HID];
    int t = threadIdx.x;
    if (t < 4 * HID) sW[t] = W[t];
    __syncthreads();
    int idx = blockIdx.x * blockDim.x + t;
    if (idx < n * HID) {
        int v = idx >> 6, c = idx & 63;
        float4 xv = ((const float4*)x)[v];
        float f = xv.x * sW[c] + xv.y * sW[64 + c] + xv.z * sW[128 + c] + xv.w * sW[192 + c];
        g_fh[idx] = __float2half(f);
    }
}

// ---------------------------------------------------------------------------
// gather-only aggregation over fp16 rows (128B/row), warp per dst node,
// two 16-lane halves on alternating edges, unrolled x2.
//   g_g[v] = f[v]*dis[v]^2 + sum f[src]*norm      (fp32 accumulate)
__global__ void k_agg_csr(int n) {
    int w = (blockIdx.x * blockDim.x + threadIdx.x) >> 5;
    int lane = threadIdx.x & 31;
    if (w >= n) return;
    int half = lane >> 4;
    int l = lane & 15;                // lane covers channels 4l..4l+3 (8B of fp16)
    int beg = g_row[w], end = g_row[w + 1];
    float dd = g_dis[w]; dd *= dd;

    float4 acc = make_float4(0.f, 0.f, 0.f, 0.f);
    if (half == 0) {
        uint2 r = ((const uint2*)(g_fh + w * HID))[l];
        float2 lo = __half22float2(*(__half2*)&r.x);
        float2 hi = __half22float2(*(__half2*)&r.y);
        acc.x = lo.x * dd; acc.y = lo.y * dd; acc.z = hi.x * dd; acc.w = hi.y * dd;
    }

    int i = beg + half;
    for (; i + 2 < end; i += 4) {
        int s0 = g_es[i],   s1 = g_es[i + 2];
        float n0 = g_en[i], n1 = g_en[i + 2];
        uint2 r0 = ((const uint2*)(g_fh + s0 * HID))[l];
        uint2 r1 = ((const uint2*)(g_fh + s1 * HID))[l];
        float2 lo0 = __half22float2(*(__half2*)&r0.x), hi0 = __half22float2(*(__half2*)&r0.y);
        float2 lo1 = __half22float2(*(__half2*)&r1.x), hi1 = __half22float2(*(__half2*)&r1.y);
        acc.x += lo0.x * n0 + lo1.x * n1;
        acc.y += lo0.y * n0 + lo1.y * n1;
        acc.z += hi0.x * n0 + hi1.x * n1;
        acc.w += hi0.y * n0 + hi1.y * n1;
    }
    if (i < end) {
        int s = g_es[i]; float nr = g_en[i];
        uint2 r = ((const uint2*)(g_fh + s * HID))[l];
        float2 lo = __half22float2(*(__half2*)&r.x), hi = __half22float2(*(__half2*)&r.y);
        acc.x += lo.x * nr; acc.y += lo.y * nr; acc.z += hi.x * nr; acc.w += hi.y * nr;
    }

    acc.x += __shfl_down_sync(0xffffffffu, acc.x, 16);
    acc.y += __shfl_down_sync(0xffffffffu, acc.y, 16);
    acc.z += __shfl_down_sync(0xffffffffu, acc.z, 16);
    acc.w += __shfl_down_sync(0xffffffffu, acc.w, 16);
    if (half == 0) ((float4*)(g_g + w * HID))[l] = acc;
}

// ---------------------------------------------------------------------------
// layer-2 GEMM, register-blocked 4 rows/thread:
//   g_fh = half( relu(g_g + b1) @ W2 )
__global__ void k_gemm64_relu(const float* __restrict__ W,
                              const float* __restrict__ bias, int n) {
    __shared__ float sW[HID * HID];    // 16 KB
    __shared__ float sx[32][HID];      // 8 KB
    __shared__ float sb[HID];
    int t = threadIdx.x;
    for (int i = t; i < HID * HID; i += 256) sW[i] = W[i];
    if (t < HID) sb[t] = bias[t];
    int wid = t >> 5, tx = t & 31;
    int base = blockIdx.x * 32;
    __syncthreads();
    for (int i = t; i < 32 * HID; i += 256) {
        int r = i >> 6, c = i & 63;
        int v = base + r;
        sx[r][c] = (v < n) ? fmaxf(g_g[v * HID + c] + sb[c], 0.f) : 0.f;
    }
    __syncthreads();
    int r0 = wid * 4;
    float acc[4][2] = {};
#pragma unroll
    for (int k = 0; k < HID; k += 4) {
        float4 xv[4];
#pragma unroll
        for (int r = 0; r < 4; r++) xv[r] = *(const float4*)&sx[r0 + r][k];
#pragma unroll
        for (int j = 0; j < 4; j++) {
            float w0 = sW[(k + j) * HID + tx];
            float w1 = sW[(k + j) * HID + tx + 32];
#pragma unroll
            for (int r = 0; r < 4; r++) {
                float xj = j == 0 ? xv[r].x : j == 1 ? xv[r].y : j == 2 ? xv[r].z : xv[r].w;
                acc[r][0] += xj * w0;
                acc[r][1] += xj * w1;
            }
        }
    }
#pragma unroll
    for (int r = 0; r < 4; r++) {
        int v = base + r0 + r;
        if (v < n) {
            g_fh[v * HID + tx]      = __float2half(acc[r][0]);
            g_fh[v * HID + tx + 32] = __float2half(acc[r][1]);
        }
    }
}

// ---------------------------------------------------------------------------
// dual projection, register-blocked: h2 = relu(g_g + b2);
//   g_Ah = half(h2 @ WA) ; g_B = h2 @ WB
__global__ void k_gemm64x2_relu(const float* __restrict__ WA, const float* __restrict__ WB,
                                const float* __restrict__ bias, int n) {
    __shared__ float sWA[HID * HID];
    __shared__ float sWB[HID * HID];
    __shared__ float sx[32][HID];
    __shared__ float sb[HID];
    int t = threadIdx.x;
    for (int i = t; i < HID * HID; i += 256) { sWA[i] = WA[i]; sWB[i] = WB[i]; }
    if (t < HID) sb[t] = bias[t];
    int wid = t >> 5, tx = t & 31;
    int base = blockIdx.x * 32;
    __syncthreads();
    for (int i = t; i < 32 * HID; i += 256) {
        int r = i >> 6, c = i & 63;
        int v = base + r;
        sx[r][c] = (v < n) ? fmaxf(g_g[v * HID + c] + sb[c], 0.f) : 0.f;
    }
    __syncthreads();
    int r0 = wid * 4;
    float accA[4][2] = {};
    float accB[4][2] = {};
#pragma unroll
    for (int k = 0; k < HID; k += 4) {
        float4 xv[4];
#pragma unroll
        for (int r = 0; r < 4; r++) xv[r] = *(const float4*)&sx[r0 + r][k];
#pragma unroll
        for (int j = 0; j < 4; j++) {
            float wa0 = sWA[(k + j) * HID + tx];
            float wa1 = sWA[(k + j) * HID + tx + 32];
            float wb0 = sWB[(k + j) * HID + tx];
            float wb1 = sWB[(k + j) * HID + tx + 32];
#pragma unroll
            for (int r = 0; r < 4; r++) {
                float xj = j == 0 ? xv[r].x : j == 1 ? xv[r].y : j == 2 ? xv[r].z : xv[r].w;
                accA[r][0] += xj * wa0;
                accA[r][1] += xj * wa1;
                accB[r][0] += xj * wb0;
                accB[r][1] += xj * wb1;
            }
        }
    }
#pragma unroll
    for (int r = 0; r < 4; r++) {
        int v = base + r0 + r;
        if (v < n) {
            g_Ah[v * HID + tx]      = __float2half(accA[r][0]);
            g_Ah[v * HID + tx + 32] = __float2half(accA[r][1]);
            g_B[v * HID + tx]       = accB[r][0];
            g_B[v * HID + tx + 32]  = accB[r][1];
        }
    }
}

// ---------------------------------------------------------------------------
// per-edge MLP over CSR order: warp per dst row, B[dst] (fp32) once per row,
// A gathered as fp16 (128B/row), unrolled x2 (4 edges in flight per warp).
__global__ void k_edge_mlp_csr(const float* __restrict__ eattr,
                               const float* __restrict__ Wm1, const float* __restrict__ bm1,
                               const float* __restrict__ Wm2, const float* __restrict__ bm2,
                               float* __restrict__ out, int n) {
    __shared__ float sWc[4 * HID];
    __shared__ float sb[HID];
    __shared__ float sW2[HID];
    __shared__ float sb2;
    int t = threadIdx.x;
    if (t < 4 * HID) sWc[t] = Wm1[128 * HID + t];
    if (t < HID) { sb[t] = bm1[t]; sW2[t] = Wm2[t]; }
    if (t == 0) sb2 = bm2[0];
    __syncthreads();

    int w = (blockIdx.x * blockDim.x + t) >> 5;
    if (w >= n) return;
    int lane = t & 31;
    int half = lane >> 4;
    int l = lane & 15;
    int c0 = l * 4;
    int beg = g_row[w], end = g_row[w + 1];
    if (beg == end) return;

    float4 b = ((const float4*)(g_B + w * HID))[l];
    float base0 = b.x + sb[c0],     base1 = b.y + sb[c0 + 1];
    float base2 = b.z + sb[c0 + 2], base3 = b.w + sb[c0 + 3];
    float w20 = sW2[c0], w21 = sW2[c0 + 1], w22 = sW2[c0 + 2], w23 = sW2[c0 + 3];
    float wc00 = sWc[c0],       wc01 = sWc[c0 + 1],       wc02 = sWc[c0 + 2],       wc03 = sWc[c0 + 3];
    float wc10 = sWc[64 + c0],  wc11 = sWc[64 + c0 + 1],  wc12 = sWc[64 + c0 + 2],  wc13 = sWc[64 + c0 + 3];
    float wc20 = sWc[128 + c0], wc21 = sWc[128 + c0 + 1], wc22 = sWc[128 + c0 + 2], wc23 = sWc[128 + c0 + 3];
    float wc30 = sWc[192 + c0], wc31 = sWc[192 + c0 + 1], wc32 = sWc[192 + c0 + 2], wc33 = sWc[192 + c0 + 3];

    for (int i = beg; i < end; i += 4) {
        int idx0 = i + half;
        int idx1 = i + 2 + half;
        float p0 = 0.f, p1 = 0.f;
        int eid0 = 0, eid1 = 0;
        bool v0 = idx0 < end, v1 = idx1 < end;
        int s0 = 0, s1 = 0;
        if (v0) { s0 = g_es[idx0]; eid0 = g_eid[idx0]; }
        if (v1) { s1 = g_es[idx1]; eid1 = g_eid[idx1]; }
        uint2 ar0 = v0 ? ((const uint2*)(g_Ah + s0 * HID))[l] : make_uint2(0, 0);
        uint2 ar1 = v1 ? ((const uint2*)(g_Ah + s1 * HID))[l] : make_uint2(0, 0);
        float4 ea0 = v0 ? ((const float4*)eattr)[eid0] : make_float4(0, 0, 0, 0);
        float4 ea1 = v1 ? ((const float4*)eattr)[eid1] : make_float4(0, 0, 0, 0);
        if (v0) {
            float2 alo = __half22float2(*(__half2*)&ar0.x);
            float2 ahi = __half22float2(*(__half2*)&ar0.y);
            float z0 = alo.x + base0 + ea0.x * wc00 + ea0.y * wc10 + ea0.z * wc20 + ea0.w * wc30;
            float z1 = alo.y + base1 + ea0.x * wc01 + ea0.y * wc11 + ea0.z * wc21 + ea0.w * wc31;
            float z2 = ahi.x + base2 + ea0.x * wc02 + ea0.y * wc12 + ea0.z * wc22 + ea0.w * wc32;
            float z3 = ahi.y + base3 + ea0.x * wc03 + ea0.y * wc13 + ea0.z * wc23 + ea0.w * wc33;
            p0 = fmaxf(z0, 0.f) * w20 + fmaxf(z1, 0.f) * w21
               + fmaxf(z2, 0.f) * w22 + fmaxf(z3, 0.f) * w23;
        }
        if (v1) {
            float2 alo = __half22float2(*(__half2*)&ar1.x);
            float2 ahi = __half22float2(*(__half2*)&ar1.y);
            float z0 = alo.x + base0 + ea1.x * wc00 + ea1.y * wc10 + ea1.z * wc20 + ea1.w * wc30;
            float z1 = alo.y + base1 + ea1.x * wc01 + ea1.y * wc11 + ea1.z * wc21 + ea1.w * wc31;
            float z2 = ahi.x + base2 + ea1.x * wc02 + ea1.y * wc12 + ea1.z * wc22 + ea1.w * wc32;
            float z3 = ahi.y + base3 + ea1.x * wc03 + ea1.y * wc13 + ea1.z * wc23 + ea1.w * wc33;
            p1 = fmaxf(z0, 0.f) * w20 + fmaxf(z1, 0.f) * w21
               + fmaxf(z2, 0.f) * w22 + fmaxf(z3, 0.f) * w23;
        }
#pragma unroll
        for (int o = 8; o; o >>= 1) {
            p0 += __shfl_xor_sync(0xffffffffu, p0, o);
            p1 += __shfl_xor_sync(0xffffffffu, p1, o);
        }
        float p0h = __shfl_sync(0xffffffffu, p0, 16);
        float p1h = __shfl_sync(0xffffffffu, p1, 16);
        int e0h = __shfl_sync(0xffffffffu, eid0, 16);
        int e1h = __shfl_sync(0xffffffffu, eid1, 16);
        if (lane == 0) {
            out[eid0] = p0 + sb2;
            if (i + 1 < end) out[e0h] = p0h + sb2;
            if (i + 2 < end) out[eid1] = p1 + sb2;
            if (i + 3 < end) out[e1h] = p1h + sb2;
        }
    }
}

// ---------------------------------------------------------------------------
extern "C" void kernel_launch(void* const* d_in, const int* in_sizes, int n_in,
                              void* d_out, int out_size) {
    const float* x    = (const float*)d_in[0];
    const int*   ei   = (const int*)d_in[1];
    const float* ea   = (const float*)d_in[2];
    const float* W1   = (const float*)d_in[3];
    const float* b1   = (const float*)d_in[4];
    const float* W2   = (const float*)d_in[5];
    const float* b2   = (const float*)d_in[6];
    const float* Wm1  = (const float*)d_in[7];
    const float* bm1  = (const float*)d_in[8];
    const float* Wm2  = (const float*)d_in[9];
    const float* bm2  = (const float*)d_in[10];
    float* out = (float*)d_out;

    int n = in_sizes[0] / 4;
    int E = in_sizes[1] / 2;

    const int T = 256;
    int gb_n  = (n + T - 1) / T;
    int gb_nh = (n * HID + T - 1) / T;
    int gb_e  = (E + T - 1) / T;
    int gb_aw = (n * 32 + T - 1) / T;           // warp per node
    int gb_g  = (n + 31) / 32;                  // 32-row GEMM tiles
    int nb    = (n + SCAN_B - 1) / SCAN_B;

    // CSR build
    k_zero_cnt<<<gb_n, T>>>(n);
    k_count<<<gb_e, T>>>(ei, E);
    k_rsqrt<<<gb_n, T>>>(n);
    k_scan_blk<<<nb, SCAN_B>>>(n);
    k_scan_top<<<1, 1024>>>(nb);
    k_scan_add<<<gb_n, T>>>(n, E);
    k_scatter<<<gb_e, T>>>(ei, E);

    // layer 1
    k_gemm4<<<gb_nh, T>>>(x, W1, n);
    k_agg_csr<<<gb_aw, T>>>(n);

    // layer 2
    k_gemm64_relu<<<gb_g, T>>>(W2, b1, n);
    k_agg_csr<<<gb_aw, T>>>(n);

    // A/B projections
    k_gemm64x2_relu<<<gb_g, T>>>(Wm1, Wm1 + 64 * HID, b2, n);

    // per-edge MLP over CSR order
    k_edge_mlp_csr<<<gb_aw, T>>>(ea, Wm1, bm1, Wm2, bm2, out, n);
}